// round 1
// baseline (speedup 1.0000x reference)
#include <cuda_runtime.h>
#include <cuda_bf16.h>

// Problem constants
#define BB 2
#define LL 2048
#define DD 1024
#define HH 16
#define HD 64
#define MM (BB * LL)   // 4096 rows

// Scratch (device globals; no allocations allowed)
__device__ float g_q[MM * DD];
__device__ float g_k[MM * DD];
__device__ float g_v[MM * DD];
__device__ float g_att[MM * DD];

// ---------------------------------------------------------------------------
// SGEMM: C[M,N] = A[M,K] * W[K,N], row-major. M=4096, N=K=1024.
// 128x128 block tile, BK=8, 256 threads, 8x8 micro-tile per thread.
// ---------------------------------------------------------------------------
__global__ __launch_bounds__(256) void sgemm_kernel(const float* __restrict__ A,
                                                    const float* __restrict__ W,
                                                    float* __restrict__ C) {
    const int N = DD, K = DD;
    __shared__ float As[8][128];  // transposed A tile: As[k][m]
    __shared__ float Bs[8][128];

    const int tid = threadIdx.x;
    const int tx = tid % 16;
    const int ty = tid / 16;
    const int bm = blockIdx.y * 128;
    const int bn = blockIdx.x * 128;

    float acc[8][8];
#pragma unroll
    for (int i = 0; i < 8; i++)
#pragma unroll
        for (int j = 0; j < 8; j++) acc[i][j] = 0.0f;

    const int arow = tid / 2, acol = (tid % 2) * 4;
    const int brow = tid / 32, bcol = (tid % 32) * 4;
    const float* Aptr = A + (size_t)(bm + arow) * K + acol;
    const float* Wptr = W + (size_t)brow * N + bn + bcol;

    for (int k0 = 0; k0 < K; k0 += 8) {
        float4 a4 = *(const float4*)(Aptr + k0);
        As[acol + 0][arow] = a4.x;
        As[acol + 1][arow] = a4.y;
        As[acol + 2][arow] = a4.z;
        As[acol + 3][arow] = a4.w;
        *(float4*)&Bs[brow][bcol] = *(const float4*)(Wptr + (size_t)k0 * N);
        __syncthreads();

#pragma unroll
        for (int k = 0; k < 8; k++) {
            float af[8], bf[8];
            *(float4*)&af[0] = *(const float4*)&As[k][ty * 8];
            *(float4*)&af[4] = *(const float4*)&As[k][ty * 8 + 4];
            *(float4*)&bf[0] = *(const float4*)&Bs[k][tx * 8];
            *(float4*)&bf[4] = *(const float4*)&Bs[k][tx * 8 + 4];
#pragma unroll
            for (int i = 0; i < 8; i++)
#pragma unroll
                for (int j = 0; j < 8; j++)
                    acc[i][j] = fmaf(af[i], bf[j], acc[i][j]);
        }
        __syncthreads();
    }

    float* Cptr = C + (size_t)(bm + ty * 8) * N + bn + tx * 8;
#pragma unroll
    for (int i = 0; i < 8; i++) {
        *(float4*)(Cptr + (size_t)i * N)     = *(float4*)&acc[i][0];
        *(float4*)(Cptr + (size_t)i * N + 4) = *(float4*)&acc[i][4];
    }
}

// ---------------------------------------------------------------------------
// Flash attention (causal). Q/K/V in [B, L, H*HD] row-major (natural x@W
// layout). One block = one (b, h, 64-row q tile). 256 threads (16x16),
// each thread owns a 4x4 tile of S / O.
// Dynamic smem layout (floats):
//   Qs[64][65], Ks[64][65], Vs[64][64], Ps[64][64]
// ---------------------------------------------------------------------------
#define QS_STRIDE 65
#define SM_QS 0
#define SM_KS (64 * QS_STRIDE)
#define SM_VS (2 * 64 * QS_STRIDE)
#define SM_PS (2 * 64 * QS_STRIDE + 64 * 64)
#define ATTN_SMEM_BYTES ((2 * 64 * QS_STRIDE + 2 * 64 * 64) * 4)

__global__ __launch_bounds__(256) void attn_kernel(const float* __restrict__ q,
                                                   const float* __restrict__ k,
                                                   const float* __restrict__ v,
                                                   float* __restrict__ out) {
    extern __shared__ float sm[];
    float* Qs = sm + SM_QS;  // [64][65]
    float* Ks = sm + SM_KS;  // [64][65]
    float* Vs = sm + SM_VS;  // [64][64]
    float* Ps = sm + SM_PS;  // [64][64]

    const int qt = blockIdx.x;   // 0..31
    const int h  = blockIdx.y;   // 0..15
    const int b  = blockIdx.z;   // 0..1
    const int tid = threadIdx.x;
    const int tx = tid & 15;
    const int ty = tid >> 4;

    const int qbase = qt * 64;
    const size_t head_off = (size_t)h * HD;

    // Load Q tile (transposed into padded rows)
#pragma unroll
    for (int it = 0; it < 4; it++) {
        int e = it * 1024 + tid * 4;
        int r = e >> 6, d = e & 63;
        float4 t = *(const float4*)(q + (size_t)(b * LL + qbase + r) * DD + head_off + d);
        Qs[r * QS_STRIDE + d + 0] = t.x;
        Qs[r * QS_STRIDE + d + 1] = t.y;
        Qs[r * QS_STRIDE + d + 2] = t.z;
        Qs[r * QS_STRIDE + d + 3] = t.w;
    }

    float m[4], l[4], o[4][4];
#pragma unroll
    for (int i = 0; i < 4; i++) {
        m[i] = -1e30f;
        l[i] = 0.0f;
#pragma unroll
        for (int j = 0; j < 4; j++) o[i][j] = 0.0f;
    }

    for (int kt = 0; kt <= qt; kt++) {
        const int kbase = kt * 64;
        __syncthreads();  // previous iter's PV done; Q ready on first iter
        // Load K, V tiles
#pragma unroll
        for (int it = 0; it < 4; it++) {
            int e = it * 1024 + tid * 4;
            int r = e >> 6, d = e & 63;
            size_t g = (size_t)(b * LL + kbase + r) * DD + head_off + d;
            float4 tk = *(const float4*)(k + g);
            Ks[r * QS_STRIDE + d + 0] = tk.x;
            Ks[r * QS_STRIDE + d + 1] = tk.y;
            Ks[r * QS_STRIDE + d + 2] = tk.z;
            Ks[r * QS_STRIDE + d + 3] = tk.w;
            *(float4*)&Vs[r * 64 + d] = *(const float4*)(v + g);
        }
        __syncthreads();

        // S = Q K^T * (1/sqrt(HD))
        float s[4][4];
#pragma unroll
        for (int i = 0; i < 4; i++)
#pragma unroll
            for (int j = 0; j < 4; j++) s[i][j] = 0.0f;

#pragma unroll 4
        for (int kk = 0; kk < 64; kk++) {
            float qf[4], kf[4];
#pragma unroll
            for (int i = 0; i < 4; i++) qf[i] = Qs[(4 * ty + i) * QS_STRIDE + kk];
#pragma unroll
            for (int j = 0; j < 4; j++) kf[j] = Ks[(4 * tx + j) * QS_STRIDE + kk];
#pragma unroll
            for (int i = 0; i < 4; i++)
#pragma unroll
                for (int j = 0; j < 4; j++)
                    s[i][j] = fmaf(qf[i], kf[j], s[i][j]);
        }

        const bool diag = (kt == qt);
#pragma unroll
        for (int i = 0; i < 4; i++) {
            const int qr = 4 * ty + i;
#pragma unroll
            for (int j = 0; j < 4; j++) {
                float val = s[i][j] * 0.125f;  // 1/sqrt(64)
                if (diag && (4 * tx + j) > qr) val = -1e30f;
                s[i][j] = val;
            }
        }

        // Online softmax per row (row owned by 16 lanes across tx)
#pragma unroll
        for (int i = 0; i < 4; i++) {
            float mloc = s[i][0];
#pragma unroll
            for (int j = 1; j < 4; j++) mloc = fmaxf(mloc, s[i][j]);
#pragma unroll
            for (int off = 1; off < 16; off <<= 1)
                mloc = fmaxf(mloc, __shfl_xor_sync(0xffffffffu, mloc, off));
            const float mn = fmaxf(m[i], mloc);
            const float alpha = __expf(m[i] - mn);
            m[i] = mn;
            float rs = 0.0f;
#pragma unroll
            for (int j = 0; j < 4; j++) {
                float p = __expf(s[i][j] - mn);
                s[i][j] = p;
                rs += p;
            }
#pragma unroll
            for (int off = 1; off < 16; off <<= 1)
                rs += __shfl_xor_sync(0xffffffffu, rs, off);
            l[i] = l[i] * alpha + rs;
#pragma unroll
            for (int j = 0; j < 4; j++) o[i][j] *= alpha;
        }

        // Share P tile
#pragma unroll
        for (int i = 0; i < 4; i++)
            *(float4*)&Ps[(4 * ty + i) * 64 + 4 * tx] = *(float4*)&s[i][0];
        __syncthreads();

        // O += P @ V
#pragma unroll 4
        for (int kk = 0; kk < 64; kk++) {
            float pf[4], vf[4];
#pragma unroll
            for (int i = 0; i < 4; i++) pf[i] = Ps[(4 * ty + i) * 64 + kk];
            *(float4*)&vf[0] = *(const float4*)&Vs[kk * 64 + 4 * tx];
#pragma unroll
            for (int i = 0; i < 4; i++)
#pragma unroll
                for (int j = 0; j < 4; j++)
                    o[i][j] = fmaf(pf[i], vf[j], o[i][j]);
        }
    }

    // Epilogue: normalize and store to [B, L, D] layout
#pragma unroll
    for (int i = 0; i < 4; i++) {
        const float inv = 1.0f / l[i];
        float4 r;
        r.x = o[i][0] * inv;
        r.y = o[i][1] * inv;
        r.z = o[i][2] * inv;
        r.w = o[i][3] * inv;
        *(float4*)(out + (size_t)(b * LL + qbase + 4 * ty + i) * DD + head_off + 4 * tx) = r;
    }
}

// ---------------------------------------------------------------------------
// Launch
// ---------------------------------------------------------------------------
extern "C" void kernel_launch(void* const* d_in, const int* in_sizes, int n_in,
                              void* d_out, int out_size) {
    const float* x  = (const float*)d_in[0];
    const float* Wk = (const float*)d_in[1];
    const float* Wq = (const float*)d_in[2];
    const float* Wv = (const float*)d_in[3];
    const float* Wo = (const float*)d_in[4];
    float* out = (float*)d_out;

    void *pq, *pk, *pv, *pa;
    cudaGetSymbolAddress(&pq, g_q);
    cudaGetSymbolAddress(&pk, g_k);
    cudaGetSymbolAddress(&pv, g_v);
    cudaGetSymbolAddress(&pa, g_att);
    float* gq = (float*)pq;
    float* gk = (float*)pk;
    float* gv = (float*)pv;
    float* ga = (float*)pa;

    cudaFuncSetAttribute(attn_kernel, cudaFuncAttributeMaxDynamicSharedMemorySize,
                         ATTN_SMEM_BYTES);

    dim3 gemm_grid(DD / 128, MM / 128);  // (8, 32)
    sgemm_kernel<<<gemm_grid, 256>>>(x, Wq, gq);
    sgemm_kernel<<<gemm_grid, 256>>>(x, Wk, gk);
    sgemm_kernel<<<gemm_grid, 256>>>(x, Wv, gv);

    dim3 attn_grid(LL / 64, HH, BB);  // (32, 16, 2)
    attn_kernel<<<attn_grid, 256, ATTN_SMEM_BYTES>>>(gq, gk, gv, ga);

    sgemm_kernel<<<gemm_grid, 256>>>(ga, Wo, out);
}

// round 3
// speedup vs baseline: 2.6245x; 2.6245x over previous
#include <cuda_runtime.h>
#include <cuda_bf16.h>
#include <cstdint>

// Problem constants
#define BB 2
#define LL 2048
#define DD 1024
#define HH 16
#define HD 64
#define MM (BB * LL)   // 4096 rows

// ---------------------------------------------------------------------------
// Scratch (device globals; no allocations allowed). All split-bf16 pairs.
// ---------------------------------------------------------------------------
__device__ __align__(1024) __nv_bfloat16 g_xh[MM * DD], g_xl[MM * DD];
__device__ __align__(1024) __nv_bfloat16 g_qh[MM * DD], g_ql[MM * DD];
__device__ __align__(1024) __nv_bfloat16 g_kh[MM * DD], g_kl[MM * DD];
__device__ __align__(1024) __nv_bfloat16 g_vh[MM * DD], g_vl[MM * DD];
__device__ __align__(1024) __nv_bfloat16 g_ah[MM * DD], g_al[MM * DD];
__device__ __align__(1024) __nv_bfloat16 g_wh[4][DD * DD], g_wl[4][DD * DD];

// ---------------------------------------------------------------------------
// Helpers (base sm_103-safe: mma.sync / ldmatrix / cp.async only)
// ---------------------------------------------------------------------------
__device__ __forceinline__ uint32_t smem_u32(const void* p) {
    uint32_t a;
    asm("{ .reg .u64 t; cvta.to.shared.u64 t, %1; cvt.u32.u64 %0, t; }" : "=r"(a) : "l"(p));
    return a;
}
__device__ __forceinline__ void cpa16(uint32_t dst, const void* src) {
    asm volatile("cp.async.cg.shared.global [%0], [%1], 16;" :: "r"(dst), "l"(src));
}
#define CP_COMMIT() asm volatile("cp.async.commit_group;" ::: "memory")
template <int N>
__device__ __forceinline__ void cp_wait() {
    asm volatile("cp.async.wait_group %0;" :: "n"(N) : "memory");
}
__device__ __forceinline__ void ldsm_x4(uint32_t (&r)[4], uint32_t addr) {
    asm volatile("ldmatrix.sync.aligned.m8n8.x4.shared.b16 {%0,%1,%2,%3}, [%4];"
                 : "=r"(r[0]), "=r"(r[1]), "=r"(r[2]), "=r"(r[3]) : "r"(addr));
}
__device__ __forceinline__ void ldsm_x4_t(uint32_t (&r)[4], uint32_t addr) {
    asm volatile("ldmatrix.sync.aligned.m8n8.x4.trans.shared.b16 {%0,%1,%2,%3}, [%4];"
                 : "=r"(r[0]), "=r"(r[1]), "=r"(r[2]), "=r"(r[3]) : "r"(addr));
}
__device__ __forceinline__ void mma16816(float (&d)[4], const uint32_t (&a)[4],
                                         uint32_t b0, uint32_t b1) {
    asm volatile(
        "mma.sync.aligned.m16n8k16.row.col.f32.bf16.bf16.f32 "
        "{%0,%1,%2,%3}, {%4,%5,%6,%7}, {%8,%9}, {%0,%1,%2,%3};"
        : "+f"(d[0]), "+f"(d[1]), "+f"(d[2]), "+f"(d[3])
        : "r"(a[0]), "r"(a[1]), "r"(a[2]), "r"(a[3]), "r"(b0), "r"(b1));
}
__device__ __forceinline__ uint32_t pack2(float lo, float hi) {
    __nv_bfloat162 t = __floats2bfloat162_rn(lo, hi);
    return *(uint32_t*)&t;
}
__device__ __forceinline__ void split_pack(float v0, float v1, uint32_t& h, uint32_t& l) {
    __nv_bfloat16 h0 = __float2bfloat16(v0), h1 = __float2bfloat16(v1);
    float l0 = v0 - __bfloat162float(h0), l1 = v1 - __bfloat162float(h1);
    __nv_bfloat162 hp; hp.x = h0; hp.y = h1;
    h = *(uint32_t*)&hp;
    l = pack2(l0, l1);
}

// ---------------------------------------------------------------------------
// Split-bf16 mma.sync GEMM: C[M,N] = A[M,K] * Wt[N,K]^T
// 128x128 CTA, BK=32, 3-stage cp.async, 8 warps (64x32 warp tiles).
// Smem rows padded to 40 elems (80B) for conflict-free ldmatrix.
// ---------------------------------------------------------------------------
#define GK_ASZ (128 * 40 * 2)       // 10240 B per operand array per stage
#define GK_STAGE (4 * GK_ASZ)       // 40960 B
#define GEMM_SMEM (3 * GK_STAGE)    // 122880 B

template <bool SPLIT_OUT>
__global__ __launch_bounds__(256, 1) void gemm_mma(
    const __nv_bfloat16* __restrict__ Ah, const __nv_bfloat16* __restrict__ Al,
    const __nv_bfloat16* __restrict__ Bh, const __nv_bfloat16* __restrict__ Bl,
    float* __restrict__ Cf, __nv_bfloat16* __restrict__ Ch, __nv_bfloat16* __restrict__ Cl,
    float scale) {
    extern __shared__ char smc[];
    const uint32_t smb = smem_u32(smc);
    const int tid = threadIdx.x, lane = tid & 31, wid = tid >> 5;
    const int wm = (wid & 1) * 64, wn = (wid >> 1) * 32;
    const int bm = blockIdx.y * 128, bn = blockIdx.x * 128;
    const int g = lane >> 2, tig = lane & 3;

    float acc[4][4][4];
#pragma unroll
    for (int a = 0; a < 4; a++)
#pragma unroll
        for (int b = 0; b < 4; b++)
#pragma unroll
            for (int c = 0; c < 4; c++) acc[a][b][c] = 0.0f;

    const int arr = tid >> 6;            // 0:Ah 1:Al 2:Bh 3:Bl
    const __nv_bfloat16* garr = (arr == 0) ? Ah : (arr == 1) ? Al : (arr == 2) ? Bh : Bl;
    const int r0 = (arr < 2) ? bm : bn;
    const int t64 = tid & 63;

    auto load_stage = [&](int s, int c) {
        uint32_t sbase = smb + s * GK_STAGE + arr * GK_ASZ;
#pragma unroll
        for (int i = 0; i < 8; i++) {
            int id = i * 64 + t64;
            int row = id >> 2, col = (id & 3) * 8;
            cpa16(sbase + (uint32_t)(row * 40 + col) * 2,
                  garr + (size_t)(r0 + row) * DD + c * 32 + col);
        }
    };

#pragma unroll
    for (int c = 0; c < 3; c++) { load_stage(c, c); CP_COMMIT(); }

    for (int c = 0; c < 32; c++) {
        cp_wait<2>();
        __syncthreads();
        const uint32_t sA_h = smb + (c % 3) * GK_STAGE;
        const uint32_t sA_l = sA_h + GK_ASZ;
        const uint32_t sB_h = sA_h + 2 * GK_ASZ;
        const uint32_t sB_l = sA_h + 3 * GK_ASZ;
#pragma unroll
        for (int j = 0; j < 2; j++) {
            uint32_t ah4[4][4], al4[4][4];
#pragma unroll
            for (int mi = 0; mi < 4; mi++) {
                uint32_t off = (uint32_t)(((wm + 16 * mi + (lane & 15)) * 40 +
                                           16 * j + ((lane >> 4) << 3)) * 2);
                ldsm_x4(ah4[mi], sA_h + off);
                ldsm_x4(al4[mi], sA_l + off);
            }
            uint32_t bh[4][2], bl[4][2];
#pragma unroll
            for (int p = 0; p < 2; p++) {
                uint32_t off = (uint32_t)(((wn + 16 * p + ((lane >> 4) << 3) + (lane & 7)) * 40 +
                                           16 * j + ((lane >> 3) & 1) * 8) * 2);
                uint32_t t[4];
                ldsm_x4(t, sB_h + off);
                bh[2 * p][0] = t[0]; bh[2 * p][1] = t[1];
                bh[2 * p + 1][0] = t[2]; bh[2 * p + 1][1] = t[3];
                ldsm_x4(t, sB_l + off);
                bl[2 * p][0] = t[0]; bl[2 * p][1] = t[1];
                bl[2 * p + 1][0] = t[2]; bl[2 * p + 1][1] = t[3];
            }
#pragma unroll
            for (int mi = 0; mi < 4; mi++)
#pragma unroll
                for (int ni = 0; ni < 4; ni++) {
                    mma16816(acc[mi][ni], ah4[mi], bh[ni][0], bh[ni][1]);
                    mma16816(acc[mi][ni], ah4[mi], bl[ni][0], bl[ni][1]);
                    mma16816(acc[mi][ni], al4[mi], bh[ni][0], bh[ni][1]);
                }
        }
        __syncthreads();
        if (c + 3 < 32) load_stage(c % 3, c + 3);
        CP_COMMIT();
    }

    // Epilogue
#pragma unroll
    for (int mi = 0; mi < 4; mi++) {
#pragma unroll
        for (int ni = 0; ni < 4; ni++) {
            int row0 = bm + wm + 16 * mi + g;
            int col = bn + wn + 8 * ni + 2 * tig;
            float v0 = acc[mi][ni][0] * scale, v1 = acc[mi][ni][1] * scale;
            float v2 = acc[mi][ni][2] * scale, v3 = acc[mi][ni][3] * scale;
            if (SPLIT_OUT) {
                uint32_t h, l;
                split_pack(v0, v1, h, l);
                *(uint32_t*)(Ch + (size_t)row0 * DD + col) = h;
                *(uint32_t*)(Cl + (size_t)row0 * DD + col) = l;
                split_pack(v2, v3, h, l);
                *(uint32_t*)(Ch + (size_t)(row0 + 8) * DD + col) = h;
                *(uint32_t*)(Cl + (size_t)(row0 + 8) * DD + col) = l;
            } else {
                *(float2*)(Cf + (size_t)row0 * DD + col) = make_float2(v0, v1);
                *(float2*)(Cf + (size_t)(row0 + 8) * DD + col) = make_float2(v2, v3);
            }
        }
    }
}

// ---------------------------------------------------------------------------
// Flash attention on mma.sync, split-bf16 inputs/outputs.
// CTA = 128 q-rows for one (b,h). 8 warps, each owns 16 q-rows x 64 dims.
// K tiles of 64 keys, double-buffered cp.async. Q scale folded in upstream.
// Smem rows padded to 72 elems (144B).
// ---------------------------------------------------------------------------
#define AT_QSZ (128 * 72 * 2)   // 18432
#define AT_KSZ (64 * 72 * 2)    // 9216
#define AT_STAGE (4 * AT_KSZ)   // 36864
#define ATTN_SMEM (2 * AT_QSZ + 2 * AT_STAGE)  // 110592

__global__ __launch_bounds__(256, 1) void attn_mma(
    const __nv_bfloat16* __restrict__ qh, const __nv_bfloat16* __restrict__ ql,
    const __nv_bfloat16* __restrict__ kh, const __nv_bfloat16* __restrict__ kl,
    const __nv_bfloat16* __restrict__ vh, const __nv_bfloat16* __restrict__ vl,
    __nv_bfloat16* __restrict__ oh, __nv_bfloat16* __restrict__ ol) {
    extern __shared__ char smc[];
    const uint32_t smb = smem_u32(smc);
    const int tid = threadIdx.x, lane = tid & 31, wid = tid >> 5;
    const int qt = (int)(gridDim.x - 1 - blockIdx.x);   // heavy tiles first
    const int h = blockIdx.y, b = blockIdx.z;
    const int qbase = qt * 128;
    const int g = lane >> 2, tig = lane & 3;
    const int wrow = 16 * wid;

    const uint32_t sQh = smb, sQl = smb + AT_QSZ;
    const uint32_t sKV = smb + 2 * AT_QSZ;

    // Q loads (both halves)
    {
        const int qa = tid >> 7;  // 0,1
        const __nv_bfloat16* gq = qa ? ql : qh;
        uint32_t sbase = qa ? sQl : sQh;
        int t128 = tid & 127;
#pragma unroll
        for (int i = 0; i < 8; i++) {
            int id = i * 128 + t128;
            int row = id >> 3, ch = (id & 7) * 8;
            cpa16(sbase + (uint32_t)(row * 72 + ch) * 2,
                  gq + (size_t)(b * LL + qbase + row) * DD + h * HD + ch);
        }
    }

    const int arr = tid >> 6;   // 0:Kh 1:Kl 2:Vh 3:Vl
    const __nv_bfloat16* gkv = (arr == 0) ? kh : (arr == 1) ? kl : (arr == 2) ? vh : vl;
    const int t64 = tid & 63;
    auto load_kv = [&](int st, int kb) {
        uint32_t sbase = sKV + st * AT_STAGE + arr * AT_KSZ;
#pragma unroll
        for (int i = 0; i < 8; i++) {
            int id = i * 64 + t64;
            int row = id >> 3, ch = (id & 7) * 8;
            cpa16(sbase + (uint32_t)(row * 72 + ch) * 2,
                  gkv + (size_t)(b * LL + kb + row) * DD + h * HD + ch);
        }
    };

    const int nkt = 2 * qt + 2;
    load_kv(0, 0);
    CP_COMMIT();

    float m0 = -1e30f, m1 = -1e30f, l0 = 0.0f, l1 = 0.0f;
    float o[8][4];
#pragma unroll
    for (int f = 0; f < 8; f++)
#pragma unroll
        for (int r = 0; r < 4; r++) o[f][r] = 0.0f;
    uint32_t qfh[4][4], qfl[4][4];

    for (int kt = 0; kt < nkt; kt++) {
        if (kt + 1 < nkt) load_kv((kt + 1) & 1, (kt + 1) * 64);
        CP_COMMIT();
        cp_wait<1>();
        __syncthreads();

        if (kt == 0) {
#pragma unroll
            for (int j = 0; j < 4; j++) {
                uint32_t off = (uint32_t)(((wrow + (lane & 15)) * 72 +
                                           16 * j + ((lane >> 4) << 3)) * 2);
                ldsm_x4(qfh[j], sQh + off);
                ldsm_x4(qfl[j], sQl + off);
            }
        }

        const int kb = kt * 64;
        if (kb <= qbase + wrow + 15) {  // warp has unmasked work
            const uint32_t sKh = sKV + (kt & 1) * AT_STAGE;
            const uint32_t sKl = sKh + AT_KSZ;
            const uint32_t sVh = sKh + 2 * AT_KSZ;
            const uint32_t sVl = sKh + 3 * AT_KSZ;

            float sf[8][4];
#pragma unroll
            for (int f = 0; f < 8; f++)
#pragma unroll
                for (int r = 0; r < 4; r++) sf[f][r] = 0.0f;

            // S = Qh*Kh + Qh*Kl + Ql*Kh
#pragma unroll
            for (int jj = 0; jj < 4; jj++) {
#pragma unroll
                for (int p = 0; p < 4; p++) {
                    uint32_t off = (uint32_t)(((16 * p + ((lane >> 4) << 3) + (lane & 7)) * 72 +
                                               16 * jj + ((lane >> 3) & 1) * 8) * 2);
                    uint32_t th[4], tl[4];
                    ldsm_x4(th, sKh + off);
                    ldsm_x4(tl, sKl + off);
                    mma16816(sf[2 * p], qfh[jj], th[0], th[1]);
                    mma16816(sf[2 * p], qfh[jj], tl[0], tl[1]);
                    mma16816(sf[2 * p], qfl[jj], th[0], th[1]);
                    mma16816(sf[2 * p + 1], qfh[jj], th[2], th[3]);
                    mma16816(sf[2 * p + 1], qfh[jj], tl[2], tl[3]);
                    mma16816(sf[2 * p + 1], qfl[jj], th[2], th[3]);
                }
            }

            const int row0 = qbase + wrow + g, row1 = row0 + 8;
            if (kb + 63 > qbase + wrow) {  // causal mask needed
#pragma unroll
                for (int f = 0; f < 8; f++) {
                    int col = kb + 8 * f + 2 * tig;
                    if (col > row0) sf[f][0] = -1e30f;
                    if (col + 1 > row0) sf[f][1] = -1e30f;
                    if (col > row1) sf[f][2] = -1e30f;
                    if (col + 1 > row1) sf[f][3] = -1e30f;
                }
            }

            // online softmax
            float mx0 = -1e30f, mx1 = -1e30f;
#pragma unroll
            for (int f = 0; f < 8; f++) {
                mx0 = fmaxf(mx0, fmaxf(sf[f][0], sf[f][1]));
                mx1 = fmaxf(mx1, fmaxf(sf[f][2], sf[f][3]));
            }
            mx0 = fmaxf(mx0, __shfl_xor_sync(0xffffffffu, mx0, 1));
            mx0 = fmaxf(mx0, __shfl_xor_sync(0xffffffffu, mx0, 2));
            mx1 = fmaxf(mx1, __shfl_xor_sync(0xffffffffu, mx1, 1));
            mx1 = fmaxf(mx1, __shfl_xor_sync(0xffffffffu, mx1, 2));
            const float mn0 = fmaxf(m0, mx0), mn1 = fmaxf(m1, mx1);
            const float a0 = __expf(m0 - mn0), a1 = __expf(m1 - mn1);
            m0 = mn0; m1 = mn1;
            float s0 = 0.0f, s1 = 0.0f;
#pragma unroll
            for (int f = 0; f < 8; f++) {
                sf[f][0] = __expf(sf[f][0] - mn0);
                sf[f][1] = __expf(sf[f][1] - mn0);
                sf[f][2] = __expf(sf[f][2] - mn1);
                sf[f][3] = __expf(sf[f][3] - mn1);
                s0 += sf[f][0] + sf[f][1];
                s1 += sf[f][2] + sf[f][3];
            }
            s0 += __shfl_xor_sync(0xffffffffu, s0, 1);
            s0 += __shfl_xor_sync(0xffffffffu, s0, 2);
            s1 += __shfl_xor_sync(0xffffffffu, s1, 1);
            s1 += __shfl_xor_sync(0xffffffffu, s1, 2);
            l0 = l0 * a0 + s0;
            l1 = l1 * a1 + s1;
#pragma unroll
            for (int f = 0; f < 8; f++) {
                o[f][0] *= a0; o[f][1] *= a0;
                o[f][2] *= a1; o[f][3] *= a1;
            }

            // O += Ph*Vh + Ph*Vl + Pl*Vh
#pragma unroll
            for (int j = 0; j < 4; j++) {
                uint32_t pA_h[4], pA_l[4];
                split_pack(sf[2 * j][0], sf[2 * j][1], pA_h[0], pA_l[0]);
                split_pack(sf[2 * j][2], sf[2 * j][3], pA_h[1], pA_l[1]);
                split_pack(sf[2 * j + 1][0], sf[2 * j + 1][1], pA_h[2], pA_l[2]);
                split_pack(sf[2 * j + 1][2], sf[2 * j + 1][3], pA_h[3], pA_l[3]);
#pragma unroll
                for (int p = 0; p < 4; p++) {
                    uint32_t off = (uint32_t)(((16 * j + ((lane >> 3) & 1) * 8 + (lane & 7)) * 72 +
                                               16 * p + (lane >> 4) * 8) * 2);
                    uint32_t th[4], tl[4];
                    ldsm_x4_t(th, sVh + off);
                    ldsm_x4_t(tl, sVl + off);
                    mma16816(o[2 * p], pA_h, th[0], th[1]);
                    mma16816(o[2 * p], pA_h, tl[0], tl[1]);
                    mma16816(o[2 * p], pA_l, th[0], th[1]);
                    mma16816(o[2 * p + 1], pA_h, th[2], th[3]);
                    mma16816(o[2 * p + 1], pA_h, tl[2], tl[3]);
                    mma16816(o[2 * p + 1], pA_l, th[2], th[3]);
                }
            }
        }
        __syncthreads();
    }

    // Epilogue: normalize, split, store
    const float i0 = 1.0f / l0, i1 = 1.0f / l1;
    const size_t grow0 = (size_t)(b * LL + qbase + wrow + g);
    const size_t grow1 = grow0 + 8;
#pragma unroll
    for (int f = 0; f < 8; f++) {
        int col = h * HD + 8 * f + 2 * tig;
        uint32_t hi, lo;
        split_pack(o[f][0] * i0, o[f][1] * i0, hi, lo);
        *(uint32_t*)(oh + grow0 * DD + col) = hi;
        *(uint32_t*)(ol + grow0 * DD + col) = lo;
        split_pack(o[f][2] * i1, o[f][3] * i1, hi, lo);
        *(uint32_t*)(oh + grow1 * DD + col) = hi;
        *(uint32_t*)(ol + grow1 * DD + col) = lo;
    }
}

// ---------------------------------------------------------------------------
// Conversions
// ---------------------------------------------------------------------------
__global__ __launch_bounds__(256) void conv_split(const float* __restrict__ x,
                                                  __nv_bfloat16* __restrict__ xh,
                                                  __nv_bfloat16* __restrict__ xl) {
    int i = (blockIdx.x * 256 + threadIdx.x) * 4;
    float4 v = *(const float4*)(x + i);
    float f[4] = {v.x, v.y, v.z, v.w};
    __nv_bfloat16 hh[4], ll[4];
#pragma unroll
    for (int j = 0; j < 4; j++) {
        hh[j] = __float2bfloat16(f[j]);
        ll[j] = __float2bfloat16(f[j] - __bfloat162float(hh[j]));
    }
    *(uint2*)(xh + i) = *(uint2*)hh;
    *(uint2*)(xl + i) = *(uint2*)ll;
}

__global__ __launch_bounds__(256) void conv_w(const float* __restrict__ W,
                                              __nv_bfloat16* __restrict__ Th,
                                              __nv_bfloat16* __restrict__ Tl) {
    __shared__ float t[32][33];
    const int tx = threadIdx.x, ty = threadIdx.y;  // 32 x 8
    const int n0 = blockIdx.x * 32, k0 = blockIdx.y * 32;
#pragma unroll
    for (int j = 0; j < 32; j += 8)
        t[ty + j][tx] = W[(size_t)(k0 + ty + j) * DD + n0 + tx];
    __syncthreads();
#pragma unroll
    for (int j = 0; j < 32; j += 8) {
        float v = t[tx][ty + j];
        __nv_bfloat16 hh = __float2bfloat16(v);
        __nv_bfloat16 ll = __float2bfloat16(v - __bfloat162float(hh));
        Th[(size_t)(n0 + ty + j) * DD + k0 + tx] = hh;
        Tl[(size_t)(n0 + ty + j) * DD + k0 + tx] = ll;
    }
}

// ---------------------------------------------------------------------------
// Launch
// ---------------------------------------------------------------------------
extern "C" void kernel_launch(void* const* d_in, const int* in_sizes, int n_in,
                              void* d_out, int out_size) {
    const float* x  = (const float*)d_in[0];
    const float* Wk = (const float*)d_in[1];
    const float* Wq = (const float*)d_in[2];
    const float* Wv = (const float*)d_in[3];
    const float* Wo = (const float*)d_in[4];
    float* out = (float*)d_out;

    void *p;
#define GETP(sym, var) cudaGetSymbolAddress(&p, sym); __nv_bfloat16* var = (__nv_bfloat16*)p;
    GETP(g_xh, xh) GETP(g_xl, xl)
    GETP(g_qh, qh) GETP(g_ql, ql)
    GETP(g_kh, kh) GETP(g_kl, kl)
    GETP(g_vh, vh) GETP(g_vl, vl)
    GETP(g_ah, ah) GETP(g_al, al)
    GETP(g_wh, wh) GETP(g_wl, wl)
#undef GETP

    cudaFuncSetAttribute(gemm_mma<true>, cudaFuncAttributeMaxDynamicSharedMemorySize, GEMM_SMEM);
    cudaFuncSetAttribute(gemm_mma<false>, cudaFuncAttributeMaxDynamicSharedMemorySize, GEMM_SMEM);
    cudaFuncSetAttribute(attn_mma, cudaFuncAttributeMaxDynamicSharedMemorySize, ATTN_SMEM);

    // Convert inputs
    conv_split<<<MM * DD / (256 * 4), 256>>>(x, xh, xl);
    dim3 wgrid(DD / 32, DD / 32);
    dim3 wblk(32, 8);
    conv_w<<<wgrid, wblk>>>(Wq, wh + 0 * (size_t)DD * DD, wl + 0 * (size_t)DD * DD);
    conv_w<<<wgrid, wblk>>>(Wk, wh + 1 * (size_t)DD * DD, wl + 1 * (size_t)DD * DD);
    conv_w<<<wgrid, wblk>>>(Wv, wh + 2 * (size_t)DD * DD, wl + 2 * (size_t)DD * DD);
    conv_w<<<wgrid, wblk>>>(Wo, wh + 3 * (size_t)DD * DD, wl + 3 * (size_t)DD * DD);

    // Projections (Q pre-scaled by 1/sqrt(HD))
    dim3 ggrid(DD / 128, MM / 128);  // (8, 32)
    gemm_mma<true><<<ggrid, 256, GEMM_SMEM>>>(xh, xl, wh + 0 * (size_t)DD * DD, wl + 0 * (size_t)DD * DD,
                                              nullptr, qh, ql, 0.125f);
    gemm_mma<true><<<ggrid, 256, GEMM_SMEM>>>(xh, xl, wh + 1 * (size_t)DD * DD, wl + 1 * (size_t)DD * DD,
                                              nullptr, kh, kl, 1.0f);
    gemm_mma<true><<<ggrid, 256, GEMM_SMEM>>>(xh, xl, wh + 2 * (size_t)DD * DD, wl + 2 * (size_t)DD * DD,
                                              nullptr, vh, vl, 1.0f);

    // Attention
    dim3 agrid(LL / 128, HH, BB);  // (16, 16, 2)
    attn_mma<<<agrid, 256, ATTN_SMEM>>>(qh, ql, kh, kl, vh, vl, ah, al);

    // Output projection (fp32 out)
    gemm_mma<false><<<ggrid, 256, GEMM_SMEM>>>(ah, al, wh + 3 * (size_t)DD * DD, wl + 3 * (size_t)DD * DD,
                                               out, nullptr, nullptr, 1.0f);
}

// round 4
// speedup vs baseline: 2.8652x; 1.0917x over previous
#include <cuda_runtime.h>
#include <cuda_bf16.h>
#include <cstdint>

// Problem constants
#define BB 2
#define LL 2048
#define DD 1024
#define HH 16
#define HD 64
#define MM (BB * LL)   // 4096 rows

// ---------------------------------------------------------------------------
// Scratch (device globals; no allocations allowed). All split-bf16 pairs.
// ---------------------------------------------------------------------------
__device__ __align__(1024) __nv_bfloat16 g_xh[MM * DD], g_xl[MM * DD];
__device__ __align__(1024) __nv_bfloat16 g_qh[MM * DD], g_ql[MM * DD];
__device__ __align__(1024) __nv_bfloat16 g_kh[MM * DD], g_kl[MM * DD];
__device__ __align__(1024) __nv_bfloat16 g_vh[MM * DD], g_vl[MM * DD];
__device__ __align__(1024) __nv_bfloat16 g_ah[MM * DD], g_al[MM * DD];
__device__ __align__(1024) __nv_bfloat16 g_wh[4][DD * DD], g_wl[4][DD * DD];

// ---------------------------------------------------------------------------
// Helpers (base sm_103-safe: mma.sync / ldmatrix / cp.async only)
// ---------------------------------------------------------------------------
__device__ __forceinline__ uint32_t smem_u32(const void* p) {
    uint32_t a;
    asm("{ .reg .u64 t; cvta.to.shared.u64 t, %1; cvt.u32.u64 %0, t; }" : "=r"(a) : "l"(p));
    return a;
}
__device__ __forceinline__ void cpa16(uint32_t dst, const void* src) {
    asm volatile("cp.async.cg.shared.global [%0], [%1], 16;" :: "r"(dst), "l"(src));
}
#define CP_COMMIT() asm volatile("cp.async.commit_group;" ::: "memory")
template <int N>
__device__ __forceinline__ void cp_wait() {
    asm volatile("cp.async.wait_group %0;" :: "n"(N) : "memory");
}
__device__ __forceinline__ void ldsm_x4(uint32_t (&r)[4], uint32_t addr) {
    asm volatile("ldmatrix.sync.aligned.m8n8.x4.shared.b16 {%0,%1,%2,%3}, [%4];"
                 : "=r"(r[0]), "=r"(r[1]), "=r"(r[2]), "=r"(r[3]) : "r"(addr));
}
__device__ __forceinline__ void ldsm_x4_t(uint32_t (&r)[4], uint32_t addr) {
    asm volatile("ldmatrix.sync.aligned.m8n8.x4.trans.shared.b16 {%0,%1,%2,%3}, [%4];"
                 : "=r"(r[0]), "=r"(r[1]), "=r"(r[2]), "=r"(r[3]) : "r"(addr));
}
__device__ __forceinline__ void mma16816(float (&d)[4], const uint32_t (&a)[4],
                                         uint32_t b0, uint32_t b1) {
    asm volatile(
        "mma.sync.aligned.m16n8k16.row.col.f32.bf16.bf16.f32 "
        "{%0,%1,%2,%3}, {%4,%5,%6,%7}, {%8,%9}, {%0,%1,%2,%3};"
        : "+f"(d[0]), "+f"(d[1]), "+f"(d[2]), "+f"(d[3])
        : "r"(a[0]), "r"(a[1]), "r"(a[2]), "r"(a[3]), "r"(b0), "r"(b1));
}
__device__ __forceinline__ uint32_t pack2(float lo, float hi) {
    __nv_bfloat162 t = __floats2bfloat162_rn(lo, hi);
    return *(uint32_t*)&t;
}
__device__ __forceinline__ void split_pack(float v0, float v1, uint32_t& h, uint32_t& l) {
    __nv_bfloat16 h0 = __float2bfloat16(v0), h1 = __float2bfloat16(v1);
    float l0 = v0 - __bfloat162float(h0), l1 = v1 - __bfloat162float(h1);
    __nv_bfloat162 hp; hp.x = h0; hp.y = h1;
    h = *(uint32_t*)&hp;
    l = pack2(l0, l1);
}

// ---------------------------------------------------------------------------
// Split-bf16 mma.sync GEMM: C[M,N] = A[M,K] * Wt[N,K]^T
// CTA tile 128x64, BK=32, 3-stage cp.async, 8 warps (32x32 warp tiles),
// 2 CTAs/SM. blockIdx.z selects weight set (fused QKV).
// Smem rows padded to 40 elems (80B) for conflict-free ldmatrix.
// ---------------------------------------------------------------------------
#define GA_SZ (128 * 40 * 2)        // 10240 B  (A array per stage)
#define GB_SZ (64 * 40 * 2)         // 5120 B   (B array per stage)
#define GK_STAGE (2 * GA_SZ + 2 * GB_SZ)  // 30720 B
#define GEMM_SMEM (3 * GK_STAGE)    // 92160 B

template <bool SPLIT_OUT>
__global__ __launch_bounds__(256, 2) void gemm_mma(
    const __nv_bfloat16* __restrict__ Ah, const __nv_bfloat16* __restrict__ Al,
    const __nv_bfloat16* __restrict__ Bh0, const __nv_bfloat16* __restrict__ Bl0,
    __nv_bfloat16* __restrict__ Ch0, __nv_bfloat16* __restrict__ Cl0,
    __nv_bfloat16* __restrict__ Ch1, __nv_bfloat16* __restrict__ Cl1,
    __nv_bfloat16* __restrict__ Ch2, __nv_bfloat16* __restrict__ Cl2,
    float* __restrict__ Cf) {
    extern __shared__ char smc[];
    const uint32_t smb = smem_u32(smc);
    const int tid = threadIdx.x, lane = tid & 31, wid = tid >> 5;
    const int wm = (wid & 3) * 32, wn = (wid >> 2) * 32;
    const int bm = blockIdx.y * 128, bn = blockIdx.x * 64;
    const int z = blockIdx.z;
    const int g = lane >> 2, tig = lane & 3;

    const __nv_bfloat16* Bh = Bh0 + (size_t)z * DD * DD;
    const __nv_bfloat16* Bl = Bl0 + (size_t)z * DD * DD;
    __nv_bfloat16* Ch = (z == 0) ? Ch0 : (z == 1) ? Ch1 : Ch2;
    __nv_bfloat16* Cl = (z == 0) ? Cl0 : (z == 1) ? Cl1 : Cl2;
    const float scale = (SPLIT_OUT && z == 0) ? 0.125f : 1.0f;

    float acc[2][4][4];
#pragma unroll
    for (int a = 0; a < 2; a++)
#pragma unroll
        for (int b = 0; b < 4; b++)
#pragma unroll
            for (int c = 0; c < 4; c++) acc[a][b][c] = 0.0f;

    // Stage loader: 1536 16B units; threads take u = tid + i*256, i<6.
    auto load_stage = [&](int s, int c) {
        const uint32_t sb = smb + s * GK_STAGE;
#pragma unroll
        for (int i = 0; i < 6; i++) {
            int u = tid + i * 256;
            if (u < 1024) {
                int arr = u >> 9;          // 0:Ah 1:Al
                int w = u & 511;
                int row = w >> 2, col8 = (w & 3) * 8;
                const __nv_bfloat16* src = (arr ? Al : Ah) + (size_t)(bm + row) * DD + c * 32 + col8;
                cpa16(sb + arr * GA_SZ + (uint32_t)(row * 40 + col8) * 2, src);
            } else {
                int u2 = u - 1024;
                int arr = u2 >> 8;         // 0:Bh 1:Bl
                int w = u2 & 255;
                int row = w >> 2, col8 = (w & 3) * 8;
                const __nv_bfloat16* src = (arr ? Bl : Bh) + (size_t)(bn + row) * DD + c * 32 + col8;
                cpa16(sb + 2 * GA_SZ + arr * GB_SZ + (uint32_t)(row * 40 + col8) * 2, src);
            }
        }
    };

#pragma unroll
    for (int c = 0; c < 3; c++) { load_stage(c, c); CP_COMMIT(); }

    for (int c = 0; c < 32; c++) {
        cp_wait<2>();
        __syncthreads();
        const uint32_t sA_h = smb + (c % 3) * GK_STAGE;
        const uint32_t sA_l = sA_h + GA_SZ;
        const uint32_t sB_h = sA_h + 2 * GA_SZ;
        const uint32_t sB_l = sB_h + GB_SZ;
#pragma unroll
        for (int j = 0; j < 2; j++) {
            uint32_t ah4[2][4], al4[2][4];
#pragma unroll
            for (int mi = 0; mi < 2; mi++) {
                uint32_t off = (uint32_t)(((wm + 16 * mi + (lane & 15)) * 40 +
                                           16 * j + ((lane >> 4) << 3)) * 2);
                ldsm_x4(ah4[mi], sA_h + off);
                ldsm_x4(al4[mi], sA_l + off);
            }
            uint32_t bh[4][2], bl[4][2];
#pragma unroll
            for (int p = 0; p < 2; p++) {
                uint32_t off = (uint32_t)(((wn + 16 * p + ((lane >> 4) << 3) + (lane & 7)) * 40 +
                                           16 * j + ((lane >> 3) & 1) * 8) * 2);
                uint32_t t[4];
                ldsm_x4(t, sB_h + off);
                bh[2 * p][0] = t[0]; bh[2 * p][1] = t[1];
                bh[2 * p + 1][0] = t[2]; bh[2 * p + 1][1] = t[3];
                ldsm_x4(t, sB_l + off);
                bl[2 * p][0] = t[0]; bl[2 * p][1] = t[1];
                bl[2 * p + 1][0] = t[2]; bl[2 * p + 1][1] = t[3];
            }
#pragma unroll
            for (int mi = 0; mi < 2; mi++)
#pragma unroll
                for (int ni = 0; ni < 4; ni++) {
                    mma16816(acc[mi][ni], ah4[mi], bh[ni][0], bh[ni][1]);
                    mma16816(acc[mi][ni], ah4[mi], bl[ni][0], bl[ni][1]);
                    mma16816(acc[mi][ni], al4[mi], bh[ni][0], bh[ni][1]);
                }
        }
        __syncthreads();
        if (c + 3 < 32) load_stage(c % 3, c + 3);
        CP_COMMIT();
    }

    // Epilogue
#pragma unroll
    for (int mi = 0; mi < 2; mi++) {
#pragma unroll
        for (int ni = 0; ni < 4; ni++) {
            int row0 = bm + wm + 16 * mi + g;
            int col = bn + wn + 8 * ni + 2 * tig;
            float v0 = acc[mi][ni][0] * scale, v1 = acc[mi][ni][1] * scale;
            float v2 = acc[mi][ni][2] * scale, v3 = acc[mi][ni][3] * scale;
            if (SPLIT_OUT) {
                uint32_t h, l;
                split_pack(v0, v1, h, l);
                *(uint32_t*)(Ch + (size_t)row0 * DD + col) = h;
                *(uint32_t*)(Cl + (size_t)row0 * DD + col) = l;
                split_pack(v2, v3, h, l);
                *(uint32_t*)(Ch + (size_t)(row0 + 8) * DD + col) = h;
                *(uint32_t*)(Cl + (size_t)(row0 + 8) * DD + col) = l;
            } else {
                *(float2*)(Cf + (size_t)row0 * DD + col) = make_float2(v0, v1);
                *(float2*)(Cf + (size_t)(row0 + 8) * DD + col) = make_float2(v2, v3);
            }
        }
    }
}

// ---------------------------------------------------------------------------
// Flash attention on mma.sync, split-bf16 inputs/outputs. (Unchanged from R2.)
// ---------------------------------------------------------------------------
#define AT_QSZ (128 * 72 * 2)   // 18432
#define AT_KSZ (64 * 72 * 2)    // 9216
#define AT_STAGE (4 * AT_KSZ)   // 36864
#define ATTN_SMEM (2 * AT_QSZ + 2 * AT_STAGE)  // 110592

__global__ __launch_bounds__(256, 1) void attn_mma(
    const __nv_bfloat16* __restrict__ qh, const __nv_bfloat16* __restrict__ ql,
    const __nv_bfloat16* __restrict__ kh, const __nv_bfloat16* __restrict__ kl,
    const __nv_bfloat16* __restrict__ vh, const __nv_bfloat16* __restrict__ vl,
    __nv_bfloat16* __restrict__ oh, __nv_bfloat16* __restrict__ ol) {
    extern __shared__ char smc[];
    const uint32_t smb = smem_u32(smc);
    const int tid = threadIdx.x, lane = tid & 31, wid = tid >> 5;
    const int qt = (int)(gridDim.x - 1 - blockIdx.x);   // heavy tiles first
    const int h = blockIdx.y, b = blockIdx.z;
    const int qbase = qt * 128;
    const int g = lane >> 2, tig = lane & 3;
    const int wrow = 16 * wid;

    const uint32_t sQh = smb, sQl = smb + AT_QSZ;
    const uint32_t sKV = smb + 2 * AT_QSZ;

    {
        const int qa = tid >> 7;
        const __nv_bfloat16* gq = qa ? ql : qh;
        uint32_t sbase = qa ? sQl : sQh;
        int t128 = tid & 127;
#pragma unroll
        for (int i = 0; i < 8; i++) {
            int id = i * 128 + t128;
            int row = id >> 3, ch = (id & 7) * 8;
            cpa16(sbase + (uint32_t)(row * 72 + ch) * 2,
                  gq + (size_t)(b * LL + qbase + row) * DD + h * HD + ch);
        }
    }

    const int arr = tid >> 6;   // 0:Kh 1:Kl 2:Vh 3:Vl
    const __nv_bfloat16* gkv = (arr == 0) ? kh : (arr == 1) ? kl : (arr == 2) ? vh : vl;
    const int t64 = tid & 63;
    auto load_kv = [&](int st, int kb) {
        uint32_t sbase = sKV + st * AT_STAGE + arr * AT_KSZ;
#pragma unroll
        for (int i = 0; i < 8; i++) {
            int id = i * 64 + t64;
            int row = id >> 3, ch = (id & 7) * 8;
            cpa16(sbase + (uint32_t)(row * 72 + ch) * 2,
                  gkv + (size_t)(b * LL + kb + row) * DD + h * HD + ch);
        }
    };

    const int nkt = 2 * qt + 2;
    load_kv(0, 0);
    CP_COMMIT();

    float m0 = -1e30f, m1 = -1e30f, l0 = 0.0f, l1 = 0.0f;
    float o[8][4];
#pragma unroll
    for (int f = 0; f < 8; f++)
#pragma unroll
        for (int r = 0; r < 4; r++) o[f][r] = 0.0f;
    uint32_t qfh[4][4], qfl[4][4];

    for (int kt = 0; kt < nkt; kt++) {
        if (kt + 1 < nkt) load_kv((kt + 1) & 1, (kt + 1) * 64);
        CP_COMMIT();
        cp_wait<1>();
        __syncthreads();

        if (kt == 0) {
#pragma unroll
            for (int j = 0; j < 4; j++) {
                uint32_t off = (uint32_t)(((wrow + (lane & 15)) * 72 +
                                           16 * j + ((lane >> 4) << 3)) * 2);
                ldsm_x4(qfh[j], sQh + off);
                ldsm_x4(qfl[j], sQl + off);
            }
        }

        const int kb = kt * 64;
        if (kb <= qbase + wrow + 15) {
            const uint32_t sKh = sKV + (kt & 1) * AT_STAGE;
            const uint32_t sKl = sKh + AT_KSZ;
            const uint32_t sVh = sKh + 2 * AT_KSZ;
            const uint32_t sVl = sKh + 3 * AT_KSZ;

            float sf[8][4];
#pragma unroll
            for (int f = 0; f < 8; f++)
#pragma unroll
                for (int r = 0; r < 4; r++) sf[f][r] = 0.0f;

#pragma unroll
            for (int jj = 0; jj < 4; jj++) {
#pragma unroll
                for (int p = 0; p < 4; p++) {
                    uint32_t off = (uint32_t)(((16 * p + ((lane >> 4) << 3) + (lane & 7)) * 72 +
                                               16 * jj + ((lane >> 3) & 1) * 8) * 2);
                    uint32_t th[4], tl[4];
                    ldsm_x4(th, sKh + off);
                    ldsm_x4(tl, sKl + off);
                    mma16816(sf[2 * p], qfh[jj], th[0], th[1]);
                    mma16816(sf[2 * p], qfh[jj], tl[0], tl[1]);
                    mma16816(sf[2 * p], qfl[jj], th[0], th[1]);
                    mma16816(sf[2 * p + 1], qfh[jj], th[2], th[3]);
                    mma16816(sf[2 * p + 1], qfh[jj], tl[2], tl[3]);
                    mma16816(sf[2 * p + 1], qfl[jj], th[2], th[3]);
                }
            }

            const int row0 = qbase + wrow + g, row1 = row0 + 8;
            if (kb + 63 > qbase + wrow) {
#pragma unroll
                for (int f = 0; f < 8; f++) {
                    int col = kb + 8 * f + 2 * tig;
                    if (col > row0) sf[f][0] = -1e30f;
                    if (col + 1 > row0) sf[f][1] = -1e30f;
                    if (col > row1) sf[f][2] = -1e30f;
                    if (col + 1 > row1) sf[f][3] = -1e30f;
                }
            }

            float mx0 = -1e30f, mx1 = -1e30f;
#pragma unroll
            for (int f = 0; f < 8; f++) {
                mx0 = fmaxf(mx0, fmaxf(sf[f][0], sf[f][1]));
                mx1 = fmaxf(mx1, fmaxf(sf[f][2], sf[f][3]));
            }
            mx0 = fmaxf(mx0, __shfl_xor_sync(0xffffffffu, mx0, 1));
            mx0 = fmaxf(mx0, __shfl_xor_sync(0xffffffffu, mx0, 2));
            mx1 = fmaxf(mx1, __shfl_xor_sync(0xffffffffu, mx1, 1));
            mx1 = fmaxf(mx1, __shfl_xor_sync(0xffffffffu, mx1, 2));
            const float mn0 = fmaxf(m0, mx0), mn1 = fmaxf(m1, mx1);
            const float a0 = __expf(m0 - mn0), a1 = __expf(m1 - mn1);
            m0 = mn0; m1 = mn1;
            float s0 = 0.0f, s1 = 0.0f;
#pragma unroll
            for (int f = 0; f < 8; f++) {
                sf[f][0] = __expf(sf[f][0] - mn0);
                sf[f][1] = __expf(sf[f][1] - mn0);
                sf[f][2] = __expf(sf[f][2] - mn1);
                sf[f][3] = __expf(sf[f][3] - mn1);
                s0 += sf[f][0] + sf[f][1];
                s1 += sf[f][2] + sf[f][3];
            }
            s0 += __shfl_xor_sync(0xffffffffu, s0, 1);
            s0 += __shfl_xor_sync(0xffffffffu, s0, 2);
            s1 += __shfl_xor_sync(0xffffffffu, s1, 1);
            s1 += __shfl_xor_sync(0xffffffffu, s1, 2);
            l0 = l0 * a0 + s0;
            l1 = l1 * a1 + s1;
#pragma unroll
            for (int f = 0; f < 8; f++) {
                o[f][0] *= a0; o[f][1] *= a0;
                o[f][2] *= a1; o[f][3] *= a1;
            }

#pragma unroll
            for (int j = 0; j < 4; j++) {
                uint32_t pA_h[4], pA_l[4];
                split_pack(sf[2 * j][0], sf[2 * j][1], pA_h[0], pA_l[0]);
                split_pack(sf[2 * j][2], sf[2 * j][3], pA_h[1], pA_l[1]);
                split_pack(sf[2 * j + 1][0], sf[2 * j + 1][1], pA_h[2], pA_l[2]);
                split_pack(sf[2 * j + 1][2], sf[2 * j + 1][3], pA_h[3], pA_l[3]);
#pragma unroll
                for (int p = 0; p < 4; p++) {
                    uint32_t off = (uint32_t)(((16 * j + ((lane >> 3) & 1) * 8 + (lane & 7)) * 72 +
                                               16 * p + (lane >> 4) * 8) * 2);
                    uint32_t th[4], tl[4];
                    ldsm_x4_t(th, sVh + off);
                    ldsm_x4_t(tl, sVl + off);
                    mma16816(o[2 * p], pA_h, th[0], th[1]);
                    mma16816(o[2 * p], pA_h, tl[0], tl[1]);
                    mma16816(o[2 * p], pA_l, th[0], th[1]);
                    mma16816(o[2 * p + 1], pA_h, th[2], th[3]);
                    mma16816(o[2 * p + 1], pA_h, tl[2], tl[3]);
                    mma16816(o[2 * p + 1], pA_l, th[2], th[3]);
                }
            }
        }
        __syncthreads();
    }

    const float i0 = 1.0f / l0, i1 = 1.0f / l1;
    const size_t grow0 = (size_t)(b * LL + qbase + wrow + g);
    const size_t grow1 = grow0 + 8;
#pragma unroll
    for (int f = 0; f < 8; f++) {
        int col = h * HD + 8 * f + 2 * tig;
        uint32_t hi, lo;
        split_pack(o[f][0] * i0, o[f][1] * i0, hi, lo);
        *(uint32_t*)(oh + grow0 * DD + col) = hi;
        *(uint32_t*)(ol + grow0 * DD + col) = lo;
        split_pack(o[f][2] * i1, o[f][3] * i1, hi, lo);
        *(uint32_t*)(oh + grow1 * DD + col) = hi;
        *(uint32_t*)(ol + grow1 * DD + col) = lo;
    }
}

// ---------------------------------------------------------------------------
// Conversions (fused weight transpose: z selects which W)
// ---------------------------------------------------------------------------
__global__ __launch_bounds__(256) void conv_split(const float* __restrict__ x,
                                                  __nv_bfloat16* __restrict__ xh,
                                                  __nv_bfloat16* __restrict__ xl) {
    int i = (blockIdx.x * 256 + threadIdx.x) * 4;
    float4 v = *(const float4*)(x + i);
    float f[4] = {v.x, v.y, v.z, v.w};
    __nv_bfloat16 hh[4], ll[4];
#pragma unroll
    for (int j = 0; j < 4; j++) {
        hh[j] = __float2bfloat16(f[j]);
        ll[j] = __float2bfloat16(f[j] - __bfloat162float(hh[j]));
    }
    *(uint2*)(xh + i) = *(uint2*)hh;
    *(uint2*)(xl + i) = *(uint2*)ll;
}

__global__ __launch_bounds__(256) void conv_w4(const float* __restrict__ W0,
                                               const float* __restrict__ W1,
                                               const float* __restrict__ W2,
                                               const float* __restrict__ W3,
                                               __nv_bfloat16* __restrict__ Th,
                                               __nv_bfloat16* __restrict__ Tl) {
    __shared__ float t[32][33];
    const int tx = threadIdx.x, ty = threadIdx.y;  // 32 x 8
    const int n0 = blockIdx.x * 32, k0 = blockIdx.y * 32;
    const int z = blockIdx.z;
    const float* W = (z == 0) ? W0 : (z == 1) ? W1 : (z == 2) ? W2 : W3;
    __nv_bfloat16* th = Th + (size_t)z * DD * DD;
    __nv_bfloat16* tl = Tl + (size_t)z * DD * DD;
#pragma unroll
    for (int j = 0; j < 32; j += 8)
        t[ty + j][tx] = W[(size_t)(k0 + ty + j) * DD + n0 + tx];
    __syncthreads();
#pragma unroll
    for (int j = 0; j < 32; j += 8) {
        float v = t[tx][ty + j];
        __nv_bfloat16 hh = __float2bfloat16(v);
        __nv_bfloat16 ll = __float2bfloat16(v - __bfloat162float(hh));
        th[(size_t)(n0 + ty + j) * DD + k0 + tx] = hh;
        tl[(size_t)(n0 + ty + j) * DD + k0 + tx] = ll;
    }
}

// ---------------------------------------------------------------------------
// Launch
// ---------------------------------------------------------------------------
extern "C" void kernel_launch(void* const* d_in, const int* in_sizes, int n_in,
                              void* d_out, int out_size) {
    const float* x  = (const float*)d_in[0];
    const float* Wk = (const float*)d_in[1];
    const float* Wq = (const float*)d_in[2];
    const float* Wv = (const float*)d_in[3];
    const float* Wo = (const float*)d_in[4];
    float* out = (float*)d_out;

    void *p;
#define GETP(sym, var) cudaGetSymbolAddress(&p, sym); __nv_bfloat16* var = (__nv_bfloat16*)p;
    GETP(g_xh, xh) GETP(g_xl, xl)
    GETP(g_qh, qh) GETP(g_ql, ql)
    GETP(g_kh, kh) GETP(g_kl, kl)
    GETP(g_vh, vh) GETP(g_vl, vl)
    GETP(g_ah, ah) GETP(g_al, al)
    GETP(g_wh, wh) GETP(g_wl, wl)
#undef GETP

    cudaFuncSetAttribute(gemm_mma<true>, cudaFuncAttributeMaxDynamicSharedMemorySize, GEMM_SMEM);
    cudaFuncSetAttribute(gemm_mma<false>, cudaFuncAttributeMaxDynamicSharedMemorySize, GEMM_SMEM);
    cudaFuncSetAttribute(attn_mma, cudaFuncAttributeMaxDynamicSharedMemorySize, ATTN_SMEM);

    // 1. conversions (weight order in g_wh/g_wl: 0=Wq, 1=Wk, 2=Wv, 3=Wo)
    conv_split<<<MM * DD / (256 * 4), 256>>>(x, xh, xl);
    dim3 wgrid(DD / 32, DD / 32, 4);
    dim3 wblk(32, 8);
    conv_w4<<<wgrid, wblk>>>(Wq, Wk, Wv, Wo, wh, wl);

    // 2. fused QKV projections (z: 0=Q pre-scaled 0.125, 1=K, 2=V)
    dim3 ggrid(DD / 64, MM / 128, 3);   // (16, 32, 3)
    gemm_mma<true><<<ggrid, 256, GEMM_SMEM>>>(xh, xl, wh, wl,
                                              qh, ql, kh, kl, vh, vl, nullptr);

    // 3. attention
    dim3 agrid(LL / 128, HH, BB);  // (16, 16, 2)
    attn_mma<<<agrid, 256, ATTN_SMEM>>>(qh, ql, kh, kl, vh, vl, ah, al);

    // 4. output projection (fp32 out)
    dim3 ogrid(DD / 64, MM / 128, 1);
    gemm_mma<false><<<ogrid, 256, GEMM_SMEM>>>(ah, al,
                                               wh + 3 * (size_t)DD * DD, wl + 3 * (size_t)DD * DD,
                                               nullptr, nullptr, nullptr, nullptr, nullptr, nullptr,
                                               out);
}

// round 5
// speedup vs baseline: 2.8975x; 1.0113x over previous
#include <cuda_runtime.h>
#include <cuda_bf16.h>
#include <cstdint>

// Problem constants
#define BB 2
#define LL 2048
#define DD 1024
#define HH 16
#define HD 64
#define MM (BB * LL)   // 4096 rows

// ---------------------------------------------------------------------------
// Scratch (device globals; no allocations allowed). All split-bf16 pairs.
// ---------------------------------------------------------------------------
__device__ __align__(1024) __nv_bfloat16 g_xh[MM * DD], g_xl[MM * DD];
__device__ __align__(1024) __nv_bfloat16 g_qh[MM * DD], g_ql[MM * DD];
__device__ __align__(1024) __nv_bfloat16 g_kh[MM * DD], g_kl[MM * DD];
__device__ __align__(1024) __nv_bfloat16 g_vh[MM * DD], g_vl[MM * DD];
__device__ __align__(1024) __nv_bfloat16 g_ah[MM * DD], g_al[MM * DD];
__device__ __align__(1024) __nv_bfloat16 g_wh[4][DD * DD], g_wl[4][DD * DD];

// ---------------------------------------------------------------------------
// Helpers (base sm_103-safe: mma.sync / ldmatrix / cp.async only)
// ---------------------------------------------------------------------------
__device__ __forceinline__ uint32_t smem_u32(const void* p) {
    uint32_t a;
    asm("{ .reg .u64 t; cvta.to.shared.u64 t, %1; cvt.u32.u64 %0, t; }" : "=r"(a) : "l"(p));
    return a;
}
__device__ __forceinline__ void cpa16(uint32_t dst, const void* src) {
    asm volatile("cp.async.cg.shared.global [%0], [%1], 16;" :: "r"(dst), "l"(src));
}
#define CP_COMMIT() asm volatile("cp.async.commit_group;" ::: "memory")
template <int N>
__device__ __forceinline__ void cp_wait() {
    asm volatile("cp.async.wait_group %0;" :: "n"(N) : "memory");
}
__device__ __forceinline__ void ldsm_x4(uint32_t (&r)[4], uint32_t addr) {
    asm volatile("ldmatrix.sync.aligned.m8n8.x4.shared.b16 {%0,%1,%2,%3}, [%4];"
                 : "=r"(r[0]), "=r"(r[1]), "=r"(r[2]), "=r"(r[3]) : "r"(addr));
}
__device__ __forceinline__ void ldsm_x4_t(uint32_t (&r)[4], uint32_t addr) {
    asm volatile("ldmatrix.sync.aligned.m8n8.x4.trans.shared.b16 {%0,%1,%2,%3}, [%4];"
                 : "=r"(r[0]), "=r"(r[1]), "=r"(r[2]), "=r"(r[3]) : "r"(addr));
}
__device__ __forceinline__ void mma16816(float (&d)[4], const uint32_t (&a)[4],
                                         uint32_t b0, uint32_t b1) {
    asm volatile(
        "mma.sync.aligned.m16n8k16.row.col.f32.bf16.bf16.f32 "
        "{%0,%1,%2,%3}, {%4,%5,%6,%7}, {%8,%9}, {%0,%1,%2,%3};"
        : "+f"(d[0]), "+f"(d[1]), "+f"(d[2]), "+f"(d[3])
        : "r"(a[0]), "r"(a[1]), "r"(a[2]), "r"(a[3]), "r"(b0), "r"(b1));
}
__device__ __forceinline__ uint32_t pack2(float lo, float hi) {
    __nv_bfloat162 t = __floats2bfloat162_rn(lo, hi);
    return *(uint32_t*)&t;
}
__device__ __forceinline__ void split_pack(float v0, float v1, uint32_t& h, uint32_t& l) {
    __nv_bfloat16 h0 = __float2bfloat16(v0), h1 = __float2bfloat16(v1);
    float l0 = v0 - __bfloat162float(h0), l1 = v1 - __bfloat162float(h1);
    __nv_bfloat162 hp; hp.x = h0; hp.y = h1;
    h = *(uint32_t*)&hp;
    l = pack2(l0, l1);
}

// ---------------------------------------------------------------------------
// Split-bf16 mma.sync GEMM: C[M,N] = A[M,K] * Wt[N,K]^T
// CTA tile 128x64, BK=32, 3-stage cp.async, 8 warps (32x32 warp tiles),
// 2 CTAs/SM. blockIdx.z selects weight set (fused QKV).
// ---------------------------------------------------------------------------
#define GA_SZ (128 * 40 * 2)        // 10240 B
#define GB_SZ (64 * 40 * 2)         // 5120 B
#define GK_STAGE (2 * GA_SZ + 2 * GB_SZ)  // 30720 B
#define GEMM_SMEM (3 * GK_STAGE)    // 92160 B

template <bool SPLIT_OUT>
__global__ __launch_bounds__(256, 2) void gemm_mma(
    const __nv_bfloat16* __restrict__ Ah, const __nv_bfloat16* __restrict__ Al,
    const __nv_bfloat16* __restrict__ Bh0, const __nv_bfloat16* __restrict__ Bl0,
    __nv_bfloat16* __restrict__ Ch0, __nv_bfloat16* __restrict__ Cl0,
    __nv_bfloat16* __restrict__ Ch1, __nv_bfloat16* __restrict__ Cl1,
    __nv_bfloat16* __restrict__ Ch2, __nv_bfloat16* __restrict__ Cl2,
    float* __restrict__ Cf) {
    extern __shared__ char smc[];
    const uint32_t smb = smem_u32(smc);
    const int tid = threadIdx.x, lane = tid & 31, wid = tid >> 5;
    const int wm = (wid & 3) * 32, wn = (wid >> 2) * 32;
    const int bm = blockIdx.y * 128, bn = blockIdx.x * 64;
    const int z = blockIdx.z;
    const int g = lane >> 2, tig = lane & 3;

    const __nv_bfloat16* Bh = Bh0 + (size_t)z * DD * DD;
    const __nv_bfloat16* Bl = Bl0 + (size_t)z * DD * DD;
    __nv_bfloat16* Ch = (z == 0) ? Ch0 : (z == 1) ? Ch1 : Ch2;
    __nv_bfloat16* Cl = (z == 0) ? Cl0 : (z == 1) ? Cl1 : Cl2;
    const float scale = (SPLIT_OUT && z == 0) ? 0.125f : 1.0f;

    float acc[2][4][4];
#pragma unroll
    for (int a = 0; a < 2; a++)
#pragma unroll
        for (int b = 0; b < 4; b++)
#pragma unroll
            for (int c = 0; c < 4; c++) acc[a][b][c] = 0.0f;

    auto load_stage = [&](int s, int c) {
        const uint32_t sb = smb + s * GK_STAGE;
#pragma unroll
        for (int i = 0; i < 6; i++) {
            int u = tid + i * 256;
            if (u < 1024) {
                int arr = u >> 9;
                int w = u & 511;
                int row = w >> 2, col8 = (w & 3) * 8;
                const __nv_bfloat16* src = (arr ? Al : Ah) + (size_t)(bm + row) * DD + c * 32 + col8;
                cpa16(sb + arr * GA_SZ + (uint32_t)(row * 40 + col8) * 2, src);
            } else {
                int u2 = u - 1024;
                int arr = u2 >> 8;
                int w = u2 & 255;
                int row = w >> 2, col8 = (w & 3) * 8;
                const __nv_bfloat16* src = (arr ? Bl : Bh) + (size_t)(bn + row) * DD + c * 32 + col8;
                cpa16(sb + 2 * GA_SZ + arr * GB_SZ + (uint32_t)(row * 40 + col8) * 2, src);
            }
        }
    };

#pragma unroll
    for (int c = 0; c < 3; c++) { load_stage(c, c); CP_COMMIT(); }

    for (int c = 0; c < 32; c++) {
        cp_wait<2>();
        __syncthreads();
        const uint32_t sA_h = smb + (c % 3) * GK_STAGE;
        const uint32_t sA_l = sA_h + GA_SZ;
        const uint32_t sB_h = sA_h + 2 * GA_SZ;
        const uint32_t sB_l = sB_h + GB_SZ;
#pragma unroll
        for (int j = 0; j < 2; j++) {
            uint32_t ah4[2][4], al4[2][4];
#pragma unroll
            for (int mi = 0; mi < 2; mi++) {
                uint32_t off = (uint32_t)(((wm + 16 * mi + (lane & 15)) * 40 +
                                           16 * j + ((lane >> 4) << 3)) * 2);
                ldsm_x4(ah4[mi], sA_h + off);
                ldsm_x4(al4[mi], sA_l + off);
            }
            uint32_t bh[4][2], bl[4][2];
#pragma unroll
            for (int p = 0; p < 2; p++) {
                uint32_t off = (uint32_t)(((wn + 16 * p + ((lane >> 4) << 3) + (lane & 7)) * 40 +
                                           16 * j + ((lane >> 3) & 1) * 8) * 2);
                uint32_t t[4];
                ldsm_x4(t, sB_h + off);
                bh[2 * p][0] = t[0]; bh[2 * p][1] = t[1];
                bh[2 * p + 1][0] = t[2]; bh[2 * p + 1][1] = t[3];
                ldsm_x4(t, sB_l + off);
                bl[2 * p][0] = t[0]; bl[2 * p][1] = t[1];
                bl[2 * p + 1][0] = t[2]; bl[2 * p + 1][1] = t[3];
            }
            // term-outer: same accumulator reused only every 8 MMAs
#pragma unroll
            for (int t = 0; t < 3; t++)
#pragma unroll
                for (int mi = 0; mi < 2; mi++)
#pragma unroll
                    for (int ni = 0; ni < 4; ni++) {
                        const uint32_t (&af)[4] = (t == 2) ? al4[mi] : ah4[mi];
                        const uint32_t b0 = (t == 1) ? bl[ni][0] : bh[ni][0];
                        const uint32_t b1 = (t == 1) ? bl[ni][1] : bh[ni][1];
                        mma16816(acc[mi][ni], af, b0, b1);
                    }
        }
        __syncthreads();
        if (c + 3 < 32) load_stage(c % 3, c + 3);
        CP_COMMIT();
    }

    // Epilogue
#pragma unroll
    for (int mi = 0; mi < 2; mi++) {
#pragma unroll
        for (int ni = 0; ni < 4; ni++) {
            int row0 = bm + wm + 16 * mi + g;
            int col = bn + wn + 8 * ni + 2 * tig;
            float v0 = acc[mi][ni][0] * scale, v1 = acc[mi][ni][1] * scale;
            float v2 = acc[mi][ni][2] * scale, v3 = acc[mi][ni][3] * scale;
            if (SPLIT_OUT) {
                uint32_t h, l;
                split_pack(v0, v1, h, l);
                *(uint32_t*)(Ch + (size_t)row0 * DD + col) = h;
                *(uint32_t*)(Cl + (size_t)row0 * DD + col) = l;
                split_pack(v2, v3, h, l);
                *(uint32_t*)(Ch + (size_t)(row0 + 8) * DD + col) = h;
                *(uint32_t*)(Cl + (size_t)(row0 + 8) * DD + col) = l;
            } else {
                *(float2*)(Cf + (size_t)row0 * DD + col) = make_float2(v0, v1);
                *(float2*)(Cf + (size_t)(row0 + 8) * DD + col) = make_float2(v2, v3);
            }
        }
    }
}

// ---------------------------------------------------------------------------
// Flash attention on mma.sync, split-bf16. 64 q-rows per CTA, 128 threads
// (4 warps x 16 rows), 2 CTAs/SM. K tiles of 64, double-buffered cp.async.
// ---------------------------------------------------------------------------
#define AT_ASZ (64 * 72 * 2)     // 9216 per array
#define AT_STAGE (4 * AT_ASZ)    // 36864
#define ATTN_SMEM (2 * AT_ASZ + 2 * AT_STAGE)  // 92160

__global__ __launch_bounds__(128, 2) void attn_mma(
    const __nv_bfloat16* __restrict__ qh, const __nv_bfloat16* __restrict__ ql,
    const __nv_bfloat16* __restrict__ kh, const __nv_bfloat16* __restrict__ kl,
    const __nv_bfloat16* __restrict__ vh, const __nv_bfloat16* __restrict__ vl,
    __nv_bfloat16* __restrict__ oh, __nv_bfloat16* __restrict__ ol) {
    extern __shared__ char smc[];
    const uint32_t smb = smem_u32(smc);
    const int tid = threadIdx.x, lane = tid & 31, wid = tid >> 5;
    const int qt = (int)(gridDim.x - 1 - blockIdx.x);   // heavy tiles first
    const int h = blockIdx.y, b = blockIdx.z;
    const int qbase = qt * 64;
    const int g = lane >> 2, tig = lane & 3;
    const int wrow = 16 * wid;

    const uint32_t sQh = smb, sQl = smb + AT_ASZ;
    const uint32_t sKV = smb + 2 * AT_ASZ;

    // Q load: 2 arrays x 512 16B-units, 128 threads -> 8 each
    {
        const int qa = tid >> 6;
        const __nv_bfloat16* gq = qa ? ql : qh;
        uint32_t sbase = qa ? sQl : sQh;
        int t64 = tid & 63;
#pragma unroll
        for (int i = 0; i < 8; i++) {
            int id = i * 64 + t64;
            int row = id >> 3, ch = (id & 7) * 8;
            cpa16(sbase + (uint32_t)(row * 72 + ch) * 2,
                  gq + (size_t)(b * LL + qbase + row) * DD + h * HD + ch);
        }
    }

    const int arr = wid;   // 0:Kh 1:Kl 2:Vh 3:Vl
    const __nv_bfloat16* gkv = (arr == 0) ? kh : (arr == 1) ? kl : (arr == 2) ? vh : vl;
    auto load_kv = [&](int st, int kb) {
        uint32_t sbase = sKV + st * AT_STAGE + arr * AT_ASZ;
#pragma unroll
        for (int i = 0; i < 16; i++) {
            int id = i * 32 + lane;
            int row = id >> 3, ch = (id & 7) * 8;
            cpa16(sbase + (uint32_t)(row * 72 + ch) * 2,
                  gkv + (size_t)(b * LL + kb + row) * DD + h * HD + ch);
        }
    };

    const int nkt = qt + 1;
    load_kv(0, 0);
    CP_COMMIT();

    float m0 = -1e30f, m1 = -1e30f, l0 = 0.0f, l1 = 0.0f;
    float o[8][4];
#pragma unroll
    for (int f = 0; f < 8; f++)
#pragma unroll
        for (int r = 0; r < 4; r++) o[f][r] = 0.0f;
    uint32_t qfh[4][4], qfl[4][4];

    for (int kt = 0; kt < nkt; kt++) {
        if (kt + 1 < nkt) load_kv((kt + 1) & 1, (kt + 1) * 64);
        CP_COMMIT();
        cp_wait<1>();
        __syncthreads();

        if (kt == 0) {
#pragma unroll
            for (int j = 0; j < 4; j++) {
                uint32_t off = (uint32_t)(((wrow + (lane & 15)) * 72 +
                                           16 * j + ((lane >> 4) << 3)) * 2);
                ldsm_x4(qfh[j], sQh + off);
                ldsm_x4(qfl[j], sQl + off);
            }
        }

        const int kb = kt * 64;
        const uint32_t sKh = sKV + (kt & 1) * AT_STAGE;
        const uint32_t sKl = sKh + AT_ASZ;
        const uint32_t sVh = sKh + 2 * AT_ASZ;
        const uint32_t sVl = sKh + 3 * AT_ASZ;

        float sf[8][4];
#pragma unroll
        for (int f = 0; f < 8; f++)
#pragma unroll
            for (int r = 0; r < 4; r++) sf[f][r] = 0.0f;

        // S = Qh*Kh + Qh*Kl + Ql*Kh  (acc reuse distance 2)
#pragma unroll
        for (int jj = 0; jj < 4; jj++) {
#pragma unroll
            for (int p = 0; p < 4; p++) {
                uint32_t off = (uint32_t)(((16 * p + ((lane >> 4) << 3) + (lane & 7)) * 72 +
                                           16 * jj + ((lane >> 3) & 1) * 8) * 2);
                uint32_t th[4], tl[4];
                ldsm_x4(th, sKh + off);
                ldsm_x4(tl, sKl + off);
                mma16816(sf[2 * p],     qfh[jj], th[0], th[1]);
                mma16816(sf[2 * p + 1], qfh[jj], th[2], th[3]);
                mma16816(sf[2 * p],     qfh[jj], tl[0], tl[1]);
                mma16816(sf[2 * p + 1], qfh[jj], tl[2], tl[3]);
                mma16816(sf[2 * p],     qfl[jj], th[0], th[1]);
                mma16816(sf[2 * p + 1], qfl[jj], th[2], th[3]);
            }
        }

        const int row0 = qbase + wrow + g, row1 = row0 + 8;
        if (kb + 63 > qbase + wrow) {  // diagonal tile: causal mask
#pragma unroll
            for (int f = 0; f < 8; f++) {
                int col = kb + 8 * f + 2 * tig;
                if (col > row0) sf[f][0] = -1e30f;
                if (col + 1 > row0) sf[f][1] = -1e30f;
                if (col > row1) sf[f][2] = -1e30f;
                if (col + 1 > row1) sf[f][3] = -1e30f;
            }
        }

        // online softmax
        float mx0 = -1e30f, mx1 = -1e30f;
#pragma unroll
        for (int f = 0; f < 8; f++) {
            mx0 = fmaxf(mx0, fmaxf(sf[f][0], sf[f][1]));
            mx1 = fmaxf(mx1, fmaxf(sf[f][2], sf[f][3]));
        }
        mx0 = fmaxf(mx0, __shfl_xor_sync(0xffffffffu, mx0, 1));
        mx0 = fmaxf(mx0, __shfl_xor_sync(0xffffffffu, mx0, 2));
        mx1 = fmaxf(mx1, __shfl_xor_sync(0xffffffffu, mx1, 1));
        mx1 = fmaxf(mx1, __shfl_xor_sync(0xffffffffu, mx1, 2));
        const float mn0 = fmaxf(m0, mx0), mn1 = fmaxf(m1, mx1);
        const float a0 = __expf(m0 - mn0), a1 = __expf(m1 - mn1);
        m0 = mn0; m1 = mn1;
        float s0 = 0.0f, s1 = 0.0f;
#pragma unroll
        for (int f = 0; f < 8; f++) {
            sf[f][0] = __expf(sf[f][0] - mn0);
            sf[f][1] = __expf(sf[f][1] - mn0);
            sf[f][2] = __expf(sf[f][2] - mn1);
            sf[f][3] = __expf(sf[f][3] - mn1);
            s0 += sf[f][0] + sf[f][1];
            s1 += sf[f][2] + sf[f][3];
        }
        s0 += __shfl_xor_sync(0xffffffffu, s0, 1);
        s0 += __shfl_xor_sync(0xffffffffu, s0, 2);
        s1 += __shfl_xor_sync(0xffffffffu, s1, 1);
        s1 += __shfl_xor_sync(0xffffffffu, s1, 2);
        l0 = l0 * a0 + s0;
        l1 = l1 * a1 + s1;
#pragma unroll
        for (int f = 0; f < 8; f++) {
            o[f][0] *= a0; o[f][1] *= a0;
            o[f][2] *= a1; o[f][3] *= a1;
        }

        // O += Ph*Vh + Ph*Vl + Pl*Vh
#pragma unroll
        for (int j = 0; j < 4; j++) {
            uint32_t pA_h[4], pA_l[4];
            split_pack(sf[2 * j][0], sf[2 * j][1], pA_h[0], pA_l[0]);
            split_pack(sf[2 * j][2], sf[2 * j][3], pA_h[1], pA_l[1]);
            split_pack(sf[2 * j + 1][0], sf[2 * j + 1][1], pA_h[2], pA_l[2]);
            split_pack(sf[2 * j + 1][2], sf[2 * j + 1][3], pA_h[3], pA_l[3]);
#pragma unroll
            for (int p = 0; p < 4; p++) {
                uint32_t off = (uint32_t)(((16 * j + ((lane >> 3) & 1) * 8 + (lane & 7)) * 72 +
                                           16 * p + (lane >> 4) * 8) * 2);
                uint32_t th[4], tl[4];
                ldsm_x4_t(th, sVh + off);
                ldsm_x4_t(tl, sVl + off);
                mma16816(o[2 * p],     pA_h, th[0], th[1]);
                mma16816(o[2 * p + 1], pA_h, th[2], th[3]);
                mma16816(o[2 * p],     pA_h, tl[0], tl[1]);
                mma16816(o[2 * p + 1], pA_h, tl[2], tl[3]);
                mma16816(o[2 * p],     pA_l, th[0], th[1]);
                mma16816(o[2 * p + 1], pA_l, th[2], th[3]);
            }
        }
        __syncthreads();
    }

    const float i0 = 1.0f / l0, i1 = 1.0f / l1;
    const size_t grow0 = (size_t)(b * LL + qbase + wrow + g);
    const size_t grow1 = grow0 + 8;
#pragma unroll
    for (int f = 0; f < 8; f++) {
        int col = h * HD + 8 * f + 2 * tig;
        uint32_t hi, lo;
        split_pack(o[f][0] * i0, o[f][1] * i0, hi, lo);
        *(uint32_t*)(oh + grow0 * DD + col) = hi;
        *(uint32_t*)(ol + grow0 * DD + col) = lo;
        split_pack(o[f][2] * i1, o[f][3] * i1, hi, lo);
        *(uint32_t*)(oh + grow1 * DD + col) = hi;
        *(uint32_t*)(ol + grow1 * DD + col) = lo;
    }
}

// ---------------------------------------------------------------------------
// Conversions
// ---------------------------------------------------------------------------
__global__ __launch_bounds__(256) void conv_split(const float* __restrict__ x,
                                                  __nv_bfloat16* __restrict__ xh,
                                                  __nv_bfloat16* __restrict__ xl) {
    int i = (blockIdx.x * 256 + threadIdx.x) * 4;
    float4 v = *(const float4*)(x + i);
    float f[4] = {v.x, v.y, v.z, v.w};
    __nv_bfloat16 hh[4], ll[4];
#pragma unroll
    for (int j = 0; j < 4; j++) {
        hh[j] = __float2bfloat16(f[j]);
        ll[j] = __float2bfloat16(f[j] - __bfloat162float(hh[j]));
    }
    *(uint2*)(xh + i) = *(uint2*)hh;
    *(uint2*)(xl + i) = *(uint2*)ll;
}

__global__ __launch_bounds__(256) void conv_w4(const float* __restrict__ W0,
                                               const float* __restrict__ W1,
                                               const float* __restrict__ W2,
                                               const float* __restrict__ W3,
                                               __nv_bfloat16* __restrict__ Th,
                                               __nv_bfloat16* __restrict__ Tl) {
    __shared__ float t[32][33];
    const int tx = threadIdx.x, ty = threadIdx.y;  // 32 x 8
    const int n0 = blockIdx.x * 32, k0 = blockIdx.y * 32;
    const int z = blockIdx.z;
    const float* W = (z == 0) ? W0 : (z == 1) ? W1 : (z == 2) ? W2 : W3;
    __nv_bfloat16* th = Th + (size_t)z * DD * DD;
    __nv_bfloat16* tl = Tl + (size_t)z * DD * DD;
#pragma unroll
    for (int j = 0; j < 32; j += 8)
        t[ty + j][tx] = W[(size_t)(k0 + ty + j) * DD + n0 + tx];
    __syncthreads();
#pragma unroll
    for (int j = 0; j < 32; j += 8) {
        float v = t[tx][ty + j];
        __nv_bfloat16 hh = __float2bfloat16(v);
        __nv_bfloat16 ll = __float2bfloat16(v - __bfloat162float(hh));
        th[(size_t)(n0 + ty + j) * DD + k0 + tx] = hh;
        tl[(size_t)(n0 + ty + j) * DD + k0 + tx] = ll;
    }
}

// ---------------------------------------------------------------------------
// Launch
// ---------------------------------------------------------------------------
extern "C" void kernel_launch(void* const* d_in, const int* in_sizes, int n_in,
                              void* d_out, int out_size) {
    const float* x  = (const float*)d_in[0];
    const float* Wk = (const float*)d_in[1];
    const float* Wq = (const float*)d_in[2];
    const float* Wv = (const float*)d_in[3];
    const float* Wo = (const float*)d_in[4];
    float* out = (float*)d_out;

    void *p;
#define GETP(sym, var) cudaGetSymbolAddress(&p, sym); __nv_bfloat16* var = (__nv_bfloat16*)p;
    GETP(g_xh, xh) GETP(g_xl, xl)
    GETP(g_qh, qh) GETP(g_ql, ql)
    GETP(g_kh, kh) GETP(g_kl, kl)
    GETP(g_vh, vh) GETP(g_vl, vl)
    GETP(g_ah, ah) GETP(g_al, al)
    GETP(g_wh, wh) GETP(g_wl, wl)
#undef GETP

    cudaFuncSetAttribute(gemm_mma<true>, cudaFuncAttributeMaxDynamicSharedMemorySize, GEMM_SMEM);
    cudaFuncSetAttribute(gemm_mma<false>, cudaFuncAttributeMaxDynamicSharedMemorySize, GEMM_SMEM);
    cudaFuncSetAttribute(attn_mma, cudaFuncAttributeMaxDynamicSharedMemorySize, ATTN_SMEM);

    // 1. conversions (weight order: 0=Wq, 1=Wk, 2=Wv, 3=Wo)
    conv_split<<<MM * DD / (256 * 4), 256>>>(x, xh, xl);
    dim3 wgrid(DD / 32, DD / 32, 4);
    dim3 wblk(32, 8);
    conv_w4<<<wgrid, wblk>>>(Wq, Wk, Wv, Wo, wh, wl);

    // 2. fused QKV projections (z: 0=Q pre-scaled 0.125, 1=K, 2=V)
    dim3 ggrid(DD / 64, MM / 128, 3);   // (16, 32, 3)
    gemm_mma<true><<<ggrid, 256, GEMM_SMEM>>>(xh, xl, wh, wl,
                                              qh, ql, kh, kl, vh, vl, nullptr);

    // 3. attention (64-row q tiles)
    dim3 agrid(LL / 64, HH, BB);  // (32, 16, 2)
    attn_mma<<<agrid, 128, ATTN_SMEM>>>(qh, ql, kh, kl, vh, vl, ah, al);

    // 4. output projection (fp32 out)
    dim3 ogrid(DD / 64, MM / 128, 1);
    gemm_mma<false><<<ogrid, 256, GEMM_SMEM>>>(ah, al,
                                               wh + 3 * (size_t)DD * DD, wl + 3 * (size_t)DD * DD,
                                               nullptr, nullptr, nullptr, nullptr, nullptr, nullptr,
                                               out);
}